// round 1
// baseline (speedup 1.0000x reference)
#include <cuda_runtime.h>
#include <math.h>

#define BDIM 4
#define TDIM 2048
#define CDIM 1024
#define WIN  16
#define NEGINF (-1e30f)

// Scratch (allocation-free rule: __device__ globals)
__device__ float g_q[(size_t)BDIM * TDIM * CDIM];
__device__ float g_k[(size_t)BDIM * TDIM * CDIM];
__device__ float g_v[(size_t)BDIM * TDIM * CDIM];
__device__ float g_s[(size_t)BDIM * TDIM * TDIM];
__device__ float g_y[(size_t)BDIM * TDIM * CDIM];

// ---------------------------------------------------------------------------
// 128x128x8 SGEMM, 256 threads, 8x8 microtile per thread.
//   C[m,n] = sum_k A[m,k] * B'[k,n]   (+ bias / mask epilogue)
// BT = true : B stored [N,K] row-major (NT gemm; covers x@W.T and q@k.T)
// BT = false: B stored [K,N] row-major (NN gemm; covers P@V)
// EPI = 0: C = acc (+ bias[n] if bias != nullptr)
// EPI = 1: scores epilogue: keep = (n >= m - WIN); C = keep ? acc*scale : NEGINF
//          fully-masked tiles short-circuit (no K loop).
// AVSKIP: start K loop at max(0, m0 - WIN) (exact: P is 0.0f below the band)
// ---------------------------------------------------------------------------
template <int EPI, bool BT, bool AVSKIP>
__global__ void __launch_bounds__(256)
gemm128(const float* __restrict__ A, const float* __restrict__ Bm,
        const float* __restrict__ bias, float* __restrict__ Cm,
        int N_, int K_, size_t sA, size_t sB, size_t sC, float scale)
{
    const int bz = blockIdx.z;
    A  += (size_t)bz * sA;
    Bm += (size_t)bz * sB;
    Cm += (size_t)bz * sC;

    const int m0 = blockIdx.y * 128;
    const int n0 = blockIdx.x * 128;
    const int tid = threadIdx.x;

    if (EPI == 1) {
        // tile fully outside the kept band (j >= i - WIN)?
        if (n0 + 127 < m0 - WIN) {
            const float4 f4 = make_float4(NEGINF, NEGINF, NEGINF, NEGINF);
            #pragma unroll 4
            for (int i = tid; i < 128 * 32; i += 256) {
                int r  = i >> 5;        // 32 float4 per 128-wide row
                int c4 = i & 31;
                *reinterpret_cast<float4*>(&Cm[(size_t)(m0 + r) * N_ + n0 + c4 * 4]) = f4;
            }
            return;
        }
    }

    int kstart = 0;
    if (AVSKIP) kstart = (m0 > WIN) ? (m0 - WIN) : 0;   // multiple of 16

    __shared__ float As[8][128];
    __shared__ float Bs[8][128];

    float acc[8][8];
    #pragma unroll
    for (int i = 0; i < 8; i++)
        #pragma unroll
        for (int j = 0; j < 8; j++) acc[i][j] = 0.0f;

    const int ty = tid >> 4;        // 0..15
    const int tx = tid & 15;        // 0..15

    // A-tile / BT-tile load mapping: 128 rows x 8 k, one float4 per thread
    const int la_row = tid >> 1;          // 0..127
    const int la_k   = (tid & 1) * 4;     // 0 or 4
    // NN B-tile load mapping: 8 k-rows x 128 n, one float4 per thread
    const int lb_row = tid >> 5;          // 0..7
    const int lb_col = (tid & 31) * 4;    // 0..124

    for (int k0 = kstart; k0 < K_; k0 += 8) {
        float4 a4 = *reinterpret_cast<const float4*>(&A[(size_t)(m0 + la_row) * K_ + k0 + la_k]);
        As[la_k + 0][la_row] = a4.x;
        As[la_k + 1][la_row] = a4.y;
        As[la_k + 2][la_row] = a4.z;
        As[la_k + 3][la_row] = a4.w;

        if (BT) {
            float4 b4 = *reinterpret_cast<const float4*>(&Bm[(size_t)(n0 + la_row) * K_ + k0 + la_k]);
            Bs[la_k + 0][la_row] = b4.x;
            Bs[la_k + 1][la_row] = b4.y;
            Bs[la_k + 2][la_row] = b4.z;
            Bs[la_k + 3][la_row] = b4.w;
        } else {
            float4 b4 = *reinterpret_cast<const float4*>(&Bm[(size_t)(k0 + lb_row) * N_ + n0 + lb_col]);
            *reinterpret_cast<float4*>(&Bs[lb_row][lb_col]) = b4;
        }
        __syncthreads();

        #pragma unroll
        for (int kk = 0; kk < 8; kk++) {
            float4 a0 = *reinterpret_cast<const float4*>(&As[kk][ty * 4]);
            float4 a1 = *reinterpret_cast<const float4*>(&As[kk][ty * 4 + 64]);
            float4 b0 = *reinterpret_cast<const float4*>(&Bs[kk][tx * 4]);
            float4 b1 = *reinterpret_cast<const float4*>(&Bs[kk][tx * 4 + 64]);
            float ar[8] = {a0.x, a0.y, a0.z, a0.w, a1.x, a1.y, a1.z, a1.w};
            float br[8] = {b0.x, b0.y, b0.z, b0.w, b1.x, b1.y, b1.z, b1.w};
            #pragma unroll
            for (int i = 0; i < 8; i++)
                #pragma unroll
                for (int j = 0; j < 8; j++)
                    acc[i][j] += ar[i] * br[j];
        }
        __syncthreads();
    }

    // epilogue
    #pragma unroll
    for (int ri = 0; ri < 2; ri++) {
        #pragma unroll
        for (int i = 0; i < 4; i++) {
            const int rloc = ty * 4 + i + ri * 64;
            const int r    = m0 + rloc;
            const int ai   = ri * 4 + i;
            #pragma unroll
            for (int ci = 0; ci < 2; ci++) {
                const int cloc = tx * 4 + ci * 64;
                const int c    = n0 + cloc;
                float4 o;
                float* ov = &o.x;
                #pragma unroll
                for (int j = 0; j < 4; j++) {
                    float val = acc[ai][ci * 4 + j];
                    if (EPI == 0) {
                        if (bias) val += bias[c + j];
                    } else {
                        val = ((c + j) >= (r - WIN)) ? val * scale : NEGINF;
                    }
                    ov[j] = val;
                }
                *reinterpret_cast<float4*>(&Cm[(size_t)r * N_ + c]) = o;
            }
        }
    }
}

// ---------------------------------------------------------------------------
// Row softmax over T=2048 entries, one block (256 threads) per row.
// ---------------------------------------------------------------------------
__global__ void __launch_bounds__(256)
softmax_rows(float* __restrict__ S)
{
    __shared__ float red[256];
    const int tid = threadIdx.x;
    float* p = S + (size_t)blockIdx.x * TDIM;

    float vals[8];
    float m = -3.4e38f;
    #pragma unroll
    for (int i = 0; i < 8; i++) {
        vals[i] = p[tid + i * 256];
        m = fmaxf(m, vals[i]);
    }
    red[tid] = m;
    __syncthreads();
    #pragma unroll
    for (int s = 128; s > 0; s >>= 1) {
        if (tid < s) red[tid] = fmaxf(red[tid], red[tid + s]);
        __syncthreads();
    }
    m = red[0];
    __syncthreads();

    float sum = 0.0f;
    #pragma unroll
    for (int i = 0; i < 8; i++) {
        vals[i] = __expf(vals[i] - m);   // __expf(-1e30 - m) == 0.0f exactly
        sum += vals[i];
    }
    red[tid] = sum;
    __syncthreads();
    #pragma unroll
    for (int s = 128; s > 0; s >>= 1) {
        if (tid < s) red[tid] += red[tid + s];
        __syncthreads();
    }
    const float inv = 1.0f / red[0];
    #pragma unroll
    for (int i = 0; i < 8; i++)
        p[tid + i * 256] = vals[i] * inv;
}

// ---------------------------------------------------------------------------
extern "C" void kernel_launch(void* const* d_in, const int* in_sizes, int n_in,
                              void* d_out, int out_size)
{
    const float* x  = (const float*)d_in[0];
    const float* Wq = (const float*)d_in[1];
    const float* bq = (const float*)d_in[2];
    const float* Wk = (const float*)d_in[3];
    const float* bk = (const float*)d_in[4];
    const float* Wv = (const float*)d_in[5];
    const float* bv = (const float*)d_in[6];
    const float* Wo = (const float*)d_in[7];
    const float* bo = (const float*)d_in[8];
    float* out = (float*)d_out;

    float *q, *k, *v, *s, *y;
    cudaGetSymbolAddress((void**)&q, g_q);
    cudaGetSymbolAddress((void**)&k, g_k);
    cudaGetSymbolAddress((void**)&v, g_v);
    cudaGetSymbolAddress((void**)&s, g_s);
    cudaGetSymbolAddress((void**)&y, g_y);

    const dim3 blk(256);
    const float scale = 0.03125f;  // 1/sqrt(1024)

    // Projections: [B*T, C] = x @ W.T + b   (NT)
    const dim3 gp(CDIM / 128, (BDIM * TDIM) / 128, 1);   // (8, 64)
    gemm128<0, true,  false><<<gp, blk>>>(x, Wq, bq, q, CDIM, CDIM, 0, 0, 0, 0.f);
    gemm128<0, true,  false><<<gp, blk>>>(x, Wk, bk, k, CDIM, CDIM, 0, 0, 0, 0.f);
    gemm128<0, true,  false><<<gp, blk>>>(x, Wv, bv, v, CDIM, CDIM, 0, 0, 0, 0.f);

    // Scores: per batch, S = mask(q @ k.T * scale)   (NT, band skip)
    const dim3 gs(TDIM / 128, TDIM / 128, BDIM);          // (16, 16, 4)
    gemm128<1, true,  false><<<gs, blk>>>(q, k, nullptr, s, TDIM, CDIM,
                                          (size_t)TDIM * CDIM, (size_t)TDIM * CDIM,
                                          (size_t)TDIM * TDIM, scale);

    // Softmax over rows
    softmax_rows<<<BDIM * TDIM, blk>>>(s);

    // y = P @ V   (NN, K-loop starts at band edge)
    const dim3 ga(CDIM / 128, TDIM / 128, BDIM);          // (8, 16, 4)
    gemm128<0, false, true ><<<ga, blk>>>(s, v, nullptr, y, CDIM, TDIM,
                                          (size_t)TDIM * TDIM, (size_t)TDIM * CDIM,
                                          (size_t)TDIM * CDIM, 0.f);

    // out = y @ Wo.T + bo   (NT)
    gemm128<0, true,  false><<<gp, blk>>>(y, Wo, bo, out, CDIM, CDIM, 0, 0, 0, 0.f);
}

// round 4
// speedup vs baseline: 3.1334x; 3.1334x over previous
#include <cuda_runtime.h>
#include <cuda_bf16.h>
#include <cstdint>

#define BDIM 4
#define TDIM 2048
#define CDIM 1024
#define WIN  16
#define NEGINF (-1e30f)

typedef __nv_bfloat16  bf16;
typedef __nv_bfloat162 bf162;

// ---------------- scratch (allocation-free rule: __device__ globals) --------
#define NTC ((size_t)BDIM * TDIM * CDIM)
#define NTT ((size_t)BDIM * TDIM * TDIM)
#define NCC ((size_t)CDIM * CDIM)
__device__ bf16  g_xh[NTC],  g_xl[NTC];
__device__ bf16  g_wqh[NCC], g_wql[NCC], g_wkh[NCC], g_wkl[NCC];
__device__ bf16  g_wvh[NCC], g_wvl[NCC], g_woh[NCC], g_wol[NCC];
__device__ bf16  g_qh[NTC],  g_ql[NTC],  g_kh[NTC],  g_kl[NTC];
__device__ float g_v[NTC];
__device__ bf16  g_vth[NTC], g_vtl[NTC];          // [b][c][t]
__device__ float g_s[NTT];
__device__ bf16  g_ph[NTT],  g_pl[NTT];
__device__ bf16  g_yh[NTC],  g_yl[NTC];

// ---------------- low-level helpers (sm_80-portable PTX only) ---------------
__device__ __forceinline__ uint32_t smem_u32(const void* p) {
    uint32_t a;
    asm("{ .reg .u64 t; cvta.to.shared.u64 t, %1; cvt.u32.u64 %0, t; }"
        : "=r"(a) : "l"(p));
    return a;
}
__device__ __forceinline__ uint32_t swz(uint32_t off) {      // SW128 swizzle
    return off ^ ((off >> 3) & 0x70);
}
__device__ __forceinline__ void cp16(uint32_t dst, const void* src) {
    asm volatile("cp.async.cg.shared.global [%0], [%1], 16;"
                 :: "r"(dst), "l"(src));
}
__device__ __forceinline__ void cp_commit() {
    asm volatile("cp.async.commit_group;" ::: "memory");
}
__device__ __forceinline__ void cp_wait1() {
    asm volatile("cp.async.wait_group 1;" ::: "memory");
}
__device__ __forceinline__ void cp_wait0() {
    asm volatile("cp.async.wait_group 0;" ::: "memory");
}
__device__ __forceinline__ void ldsm4(uint32_t (&r)[4], uint32_t addr) {
    asm volatile("ldmatrix.sync.aligned.m8n8.x4.shared.b16 {%0,%1,%2,%3}, [%4];"
                 : "=r"(r[0]), "=r"(r[1]), "=r"(r[2]), "=r"(r[3]) : "r"(addr));
}
__device__ __forceinline__ void mma16816(float (&c)[4], const uint32_t (&a)[4],
                                         const uint32_t (&b)[2]) {
    asm volatile(
        "mma.sync.aligned.m16n8k16.row.col.f32.bf16.bf16.f32 "
        "{%0,%1,%2,%3}, {%4,%5,%6,%7}, {%8,%9}, {%0,%1,%2,%3};"
        : "+f"(c[0]), "+f"(c[1]), "+f"(c[2]), "+f"(c[3])
        : "r"(a[0]), "r"(a[1]), "r"(a[2]), "r"(a[3]), "r"(b[0]), "r"(b[1]));
}
__device__ __forceinline__ void split1(float v, bf16& h, bf16& l) {
    h = __float2bfloat16_rn(v);
    l = __float2bfloat16_rn(v - __bfloat162float(h));
}
__device__ __forceinline__ void split_store2(bf16* H, bf16* L, size_t idx,
                                             float v0, float v1) {
    bf16 h0, l0, h1, l1;
    split1(v0, h0, l0);
    split1(v1, h1, l1);
    *reinterpret_cast<bf162*>(&H[idx]) = bf162(h0, h1);
    *reinterpret_cast<bf162*>(&L[idx]) = bf162(l0, l1);
}

// ---------------------------------------------------------------------------
// Pipelined mma.sync GEMM (NT): C[m,n] = sum_k A[m,k]*B[n,k]
// A,B given as bf16 hi/lo pairs, K-major.  fp32 accuracy: AhBh+AhBl+AlBh.
// CTA 128x128, BK=64, 8 warps (4x2), warp tile 32x64, 2-stage cp.async.
// EPI 0: fp32 out + bias.  EPI 1: masked score out (fp32).
// EPI 2: bf16 hi/lo pair out (+bias if non-null).
// AVSKIP: start K at m0-64 (P is exactly 0 below the band).
// ---------------------------------------------------------------------------
#define STAGE_BYTES 65536          // 4 tiles x (128 rows x 128B)
#define SMEM_SZ     (2 * STAGE_BYTES)

template <int EPI, bool AVSKIP>
__global__ void __launch_bounds__(256)
gemm_mma(const bf16* __restrict__ Ah, const bf16* __restrict__ Al,
         const bf16* __restrict__ Bh, const bf16* __restrict__ Bl,
         const float* __restrict__ bias,
         float* __restrict__ Cf, bf16* __restrict__ Ch, bf16* __restrict__ Cl,
         int N_, int K_, size_t sA, size_t sB, size_t sC, float scale)
{
    extern __shared__ __align__(1024) char smem[];
    const int bz = blockIdx.z;
    Ah += (size_t)bz * sA;  Al += (size_t)bz * sA;
    Bh += (size_t)bz * sB;  Bl += (size_t)bz * sB;
    const size_t cOff = (size_t)bz * sC;

    const int m0 = blockIdx.y * 128;
    const int n0 = blockIdx.x * 128;
    const int tid = threadIdx.x;

    if (EPI == 1) {        // fully-masked score tile: write NEGINF, done
        if (n0 + 127 < m0 - WIN) {
            const float4 f4 = make_float4(NEGINF, NEGINF, NEGINF, NEGINF);
            #pragma unroll 4
            for (int i = tid; i < 128 * 32; i += 256) {
                int r = i >> 5, c4 = i & 31;
                *reinterpret_cast<float4*>(&Cf[cOff + (size_t)(m0 + r) * N_ + n0 + c4 * 4]) = f4;
            }
            return;
        }
    }

    int kstart = 0;
    if (AVSKIP) kstart = (m0 >= 64) ? m0 - 64 : 0;

    const uint32_t sbase = smem_u32(smem);

    auto load_stage = [&](int stg, int k0) {
        const uint32_t sb = sbase + stg * STAGE_BYTES;
        #pragma unroll
        for (int i = 0; i < 4; i++) {
            const int id = tid + i * 256;            // 1024 16B-chunks per tile
            const int row = id >> 3, kc = id & 7;
            const uint32_t d = swz((uint32_t)(row * 128 + kc * 16));
            const size_t ga = (size_t)(m0 + row) * K_ + k0 + kc * 8;
            const size_t gb = (size_t)(n0 + row) * K_ + k0 + kc * 8;
            cp16(sb +         d, Ah + ga);
            cp16(sb + 16384 + d, Al + ga);
            cp16(sb + 32768 + d, Bh + gb);
            cp16(sb + 49152 + d, Bl + gb);
        }
    };

    const int wid = tid >> 5, lane = tid & 31;
    const int warpM = wid & 3, warpN = wid >> 2;

    float acc[2][8][4];
    #pragma unroll
    for (int i = 0; i < 2; i++)
        #pragma unroll
        for (int j = 0; j < 8; j++)
            #pragma unroll
            for (int t = 0; t < 4; t++) acc[i][j][t] = 0.0f;

    // ldmatrix per-lane base byte offsets inside a tile
    const uint32_t aoff = (uint32_t)((warpM * 32 + (lane & 15)) * 128 + (lane >> 4) * 16);
    const int bgrp = lane >> 3, bl8 = lane & 7;
    const uint32_t boff = (uint32_t)((warpN * 64 + (bgrp >> 1) * 8 + bl8) * 128 + (bgrp & 1) * 16);

    load_stage(0, kstart);
    cp_commit();

    int stg = 0;
    for (int k0 = kstart; k0 < K_; k0 += 64) {
        const int kn = k0 + 64;
        if (kn < K_) load_stage(stg ^ 1, kn);
        cp_commit();
        if (kn < K_) cp_wait1(); else cp_wait0();
        __syncthreads();

        const uint32_t tb  = sbase + stg * STAGE_BYTES;
        const uint32_t tAh = tb, tAl = tb + 16384, tBh = tb + 32768, tBl = tb + 49152;

        #pragma unroll
        for (int kk = 0; kk < 4; kk++) {              // 4 k-steps of 16
            const uint32_t ka = kk * 32;              // 16 bf16 = 32 bytes
            uint32_t ah[2][4], al[2][4];
            #pragma unroll
            for (int mi = 0; mi < 2; mi++) {
                const uint32_t off = aoff + mi * 2048 + ka;
                ldsm4(ah[mi], tAh + swz(off));
                ldsm4(al[mi], tAl + swz(off));
            }
            #pragma unroll
            for (int h = 0; h < 2; h++) {             // two n-halves of 32
                uint32_t bh_[4][2], bl_[4][2];
                #pragma unroll
                for (int p = 0; p < 2; p++) {         // each ldsm4 covers 2 n-tiles
                    const uint32_t off = boff + (uint32_t)((h * 32 + p * 16) * 128) + ka;
                    uint32_t t4[4];
                    ldsm4(t4, tBh + swz(off));
                    bh_[p * 2][0] = t4[0]; bh_[p * 2][1] = t4[1];
                    bh_[p * 2 + 1][0] = t4[2]; bh_[p * 2 + 1][1] = t4[3];
                    ldsm4(t4, tBl + swz(off));
                    bl_[p * 2][0] = t4[0]; bl_[p * 2][1] = t4[1];
                    bl_[p * 2 + 1][0] = t4[2]; bl_[p * 2 + 1][1] = t4[3];
                }
                #pragma unroll
                for (int mi = 0; mi < 2; mi++)
                    #pragma unroll
                    for (int ni = 0; ni < 4; ni++) {
                        mma16816(acc[mi][h * 4 + ni], ah[mi], bh_[ni]);
                        mma16816(acc[mi][h * 4 + ni], ah[mi], bl_[ni]);
                        mma16816(acc[mi][h * 4 + ni], al[mi], bh_[ni]);
                    }
            }
        }
        __syncthreads();
        stg ^= 1;
    }

    // ---- epilogue ----
    const int rbase = m0 + warpM * 32 + (lane >> 2);
    const int cbase = n0 + warpN * 64 + (lane & 3) * 2;
    #pragma unroll
    for (int mi = 0; mi < 2; mi++) {
        const int ra = rbase + mi * 16, rb = ra + 8;
        #pragma unroll
        for (int ni = 0; ni < 8; ni++) {
            const int c = cbase + ni * 8;
            float v0 = acc[mi][ni][0], v1 = acc[mi][ni][1];
            float v2 = acc[mi][ni][2], v3 = acc[mi][ni][3];
            if (EPI == 0) {
                const float b0 = bias[c], b1 = bias[c + 1];
                *reinterpret_cast<float2*>(&Cf[cOff + (size_t)ra * N_ + c]) =
                    make_float2(v0 + b0, v1 + b1);
                *reinterpret_cast<float2*>(&Cf[cOff + (size_t)rb * N_ + c]) =
                    make_float2(v2 + b0, v3 + b1);
            } else if (EPI == 1) {
                float2 o;
                o.x = (c     >= ra - WIN) ? v0 * scale : NEGINF;
                o.y = (c + 1 >= ra - WIN) ? v1 * scale : NEGINF;
                *reinterpret_cast<float2*>(&Cf[cOff + (size_t)ra * N_ + c]) = o;
                o.x = (c     >= rb - WIN) ? v2 * scale : NEGINF;
                o.y = (c + 1 >= rb - WIN) ? v3 * scale : NEGINF;
                *reinterpret_cast<float2*>(&Cf[cOff + (size_t)rb * N_ + c]) = o;
            } else {
                float b0 = 0.f, b1 = 0.f;
                if (bias) { b0 = bias[c]; b1 = bias[c + 1]; }
                split_store2(Ch, Cl, cOff + (size_t)ra * N_ + c, v0 + b0, v1 + b1);
                split_store2(Ch, Cl, cOff + (size_t)rb * N_ + c, v2 + b0, v3 + b1);
            }
        }
    }
}

// ---------------------------------------------------------------------------
// fp32 -> bf16 hi/lo elementwise split (vectorized by 4)
// ---------------------------------------------------------------------------
__global__ void __launch_bounds__(256)
split_kernel(const float* __restrict__ X, bf16* __restrict__ H,
             bf16* __restrict__ L, int n4)
{
    const int i = blockIdx.x * 256 + threadIdx.x;
    if (i >= n4) return;
    const float4 v = reinterpret_cast<const float4*>(X)[i];
    bf16 h0, l0, h1, l1, h2, l2, h3, l3;
    split1(v.x, h0, l0); split1(v.y, h1, l1);
    split1(v.z, h2, l2); split1(v.w, h3, l3);
    reinterpret_cast<bf162*>(H)[2 * i]     = bf162(h0, h1);
    reinterpret_cast<bf162*>(H)[2 * i + 1] = bf162(h2, h3);
    reinterpret_cast<bf162*>(L)[2 * i]     = bf162(l0, l1);
    reinterpret_cast<bf162*>(L)[2 * i + 1] = bf162(l2, l3);
}

// ---------------------------------------------------------------------------
// V transpose + split: VtH/VtL[b][c][t] = split(V[b][t][c])
// ---------------------------------------------------------------------------
__global__ void __launch_bounds__(256)
transpose_split(const float* __restrict__ V, bf16* __restrict__ TH,
                bf16* __restrict__ TL)
{
    __shared__ float t[32][33];
    const int b = blockIdx.z;
    const int c0 = blockIdx.x * 32, t0 = blockIdx.y * 32;
    const float* Vb = V + (size_t)b * TDIM * CDIM;
    bf16* THb = TH + (size_t)b * TDIM * CDIM;
    bf16* TLb = TL + (size_t)b * TDIM * CDIM;
    const int tx = threadIdx.x, ty = threadIdx.y;
    #pragma unroll
    for (int i = 0; i < 32; i += 8)
        t[ty + i][tx] = Vb[(size_t)(t0 + ty + i) * CDIM + c0 + tx];
    __syncthreads();
    #pragma unroll
    for (int i = 0; i < 32; i += 8) {
        bf16 h, l;
        split1(t[tx][ty + i], h, l);
        const size_t idx = (size_t)(c0 + ty + i) * TDIM + t0 + tx;
        THb[idx] = h;
        TLb[idx] = l;
    }
}

// ---------------------------------------------------------------------------
// Row softmax over T=2048 (one 256-thread block per row); writes P hi/lo bf16
// ---------------------------------------------------------------------------
__global__ void __launch_bounds__(256)
softmax_rows(const float* __restrict__ S, bf16* __restrict__ PH,
             bf16* __restrict__ PL)
{
    __shared__ float red[256];
    const int tid = threadIdx.x;
    const size_t roff = (size_t)blockIdx.x * TDIM;
    const float* p = S + roff;

    float vals[8];
    float m = -3.4e38f;
    #pragma unroll
    for (int i = 0; i < 8; i++) {
        vals[i] = p[tid + i * 256];
        m = fmaxf(m, vals[i]);
    }
    red[tid] = m;
    __syncthreads();
    #pragma unroll
    for (int s = 128; s > 0; s >>= 1) {
        if (tid < s) red[tid] = fmaxf(red[tid], red[tid + s]);
        __syncthreads();
    }
    m = red[0];
    __syncthreads();

    float sum = 0.0f;
    #pragma unroll
    for (int i = 0; i < 8; i++) {
        vals[i] = __expf(vals[i] - m);       // exact 0 for masked entries
        sum += vals[i];
    }
    red[tid] = sum;
    __syncthreads();
    #pragma unroll
    for (int s = 128; s > 0; s >>= 1) {
        if (tid < s) red[tid] += red[tid + s];
        __syncthreads();
    }
    const float inv = 1.0f / red[0];
    #pragma unroll
    for (int i = 0; i < 8; i++) {
        bf16 h, l;
        split1(vals[i] * inv, h, l);
        PH[roff + tid + i * 256] = h;
        PL[roff + tid + i * 256] = l;
    }
}

// ---------------------------------------------------------------------------
extern "C" void kernel_launch(void* const* d_in, const int* in_sizes, int n_in,
                              void* d_out, int out_size)
{
    const float* x  = (const float*)d_in[0];
    const float* Wq = (const float*)d_in[1];
    const float* bq = (const float*)d_in[2];
    const float* Wk = (const float*)d_in[3];
    const float* bk = (const float*)d_in[4];
    const float* Wv = (const float*)d_in[5];
    const float* bv = (const float*)d_in[6];
    const float* Wo = (const float*)d_in[7];
    const float* bo = (const float*)d_in[8];
    float* out = (float*)d_out;

    bf16 *xh, *xl, *wqh, *wql, *wkh, *wkl, *wvh, *wvl, *woh, *wol;
    bf16 *qh, *ql, *kh, *kl, *vth, *vtl, *ph, *pl, *yh, *yl;
    float *v, *s;
    cudaGetSymbolAddress((void**)&xh, g_xh);   cudaGetSymbolAddress((void**)&xl, g_xl);
    cudaGetSymbolAddress((void**)&wqh, g_wqh); cudaGetSymbolAddress((void**)&wql, g_wql);
    cudaGetSymbolAddress((void**)&wkh, g_wkh); cudaGetSymbolAddress((void**)&wkl, g_wkl);
    cudaGetSymbolAddress((void**)&wvh, g_wvh); cudaGetSymbolAddress((void**)&wvl, g_wvl);
    cudaGetSymbolAddress((void**)&woh, g_woh); cudaGetSymbolAddress((void**)&wol, g_wol);
    cudaGetSymbolAddress((void**)&qh, g_qh);   cudaGetSymbolAddress((void**)&ql, g_ql);
    cudaGetSymbolAddress((void**)&kh, g_kh);   cudaGetSymbolAddress((void**)&kl, g_kl);
    cudaGetSymbolAddress((void**)&v, g_v);
    cudaGetSymbolAddress((void**)&vth, g_vth); cudaGetSymbolAddress((void**)&vtl, g_vtl);
    cudaGetSymbolAddress((void**)&s, g_s);
    cudaGetSymbolAddress((void**)&ph, g_ph);   cudaGetSymbolAddress((void**)&pl, g_pl);
    cudaGetSymbolAddress((void**)&yh, g_yh);   cudaGetSymbolAddress((void**)&yl, g_yl);

    cudaFuncSetAttribute(gemm_mma<0, false>, cudaFuncAttributeMaxDynamicSharedMemorySize, SMEM_SZ);
    cudaFuncSetAttribute(gemm_mma<1, false>, cudaFuncAttributeMaxDynamicSharedMemorySize, SMEM_SZ);
    cudaFuncSetAttribute(gemm_mma<2, false>, cudaFuncAttributeMaxDynamicSharedMemorySize, SMEM_SZ);
    cudaFuncSetAttribute(gemm_mma<2, true >, cudaFuncAttributeMaxDynamicSharedMemorySize, SMEM_SZ);

    const dim3 blk(256);
    const float scale = 0.03125f;  // 1/sqrt(1024)
    const size_t sTC = (size_t)TDIM * CDIM;
    const size_t sTT = (size_t)TDIM * TDIM;

    // Pre-split inputs and weights into bf16 hi/lo
    split_kernel<<<(int)(NTC / 4 / 256), blk>>>(x, xh, xl, (int)(NTC / 4));
    split_kernel<<<(int)(NCC / 4 / 256), blk>>>(Wq, wqh, wql, (int)(NCC / 4));
    split_kernel<<<(int)(NCC / 4 / 256), blk>>>(Wk, wkh, wkl, (int)(NCC / 4));
    split_kernel<<<(int)(NCC / 4 / 256), blk>>>(Wv, wvh, wvl, (int)(NCC / 4));
    split_kernel<<<(int)(NCC / 4 / 256), blk>>>(Wo, woh, wol, (int)(NCC / 4));

    // Projections: q,k written as hi/lo pairs; v as fp32 (for transpose)
    const dim3 gp(CDIM / 128, (BDIM * TDIM) / 128, 1);       // (8, 64)
    gemm_mma<2, false><<<gp, blk, SMEM_SZ>>>(xh, xl, wqh, wql, bq,
                                             nullptr, qh, ql, CDIM, CDIM, 0, 0, 0, 0.f);
    gemm_mma<2, false><<<gp, blk, SMEM_SZ>>>(xh, xl, wkh, wkl, bk,
                                             nullptr, kh, kl, CDIM, CDIM, 0, 0, 0, 0.f);
    gemm_mma<0, false><<<gp, blk, SMEM_SZ>>>(xh, xl, wvh, wvl, bv,
                                             v, nullptr, nullptr, CDIM, CDIM, 0, 0, 0, 0.f);

    // V transpose + split -> [b][c][t] hi/lo
    transpose_split<<<dim3(CDIM / 32, TDIM / 32, BDIM), dim3(32, 8)>>>(v, vth, vtl);

    // Scores: S = mask(q @ k.T * scale), fp32
    const dim3 gs(TDIM / 128, TDIM / 128, BDIM);             // (16, 16, 4)
    gemm_mma<1, false><<<gs, blk, SMEM_SZ>>>(qh, ql, kh, kl, nullptr,
                                             s, nullptr, nullptr, TDIM, CDIM,
                                             sTC, sTC, sTT, scale);

    // Softmax -> P hi/lo
    softmax_rows<<<BDIM * TDIM, blk>>>(s, ph, pl);

    // y = P @ Vt.T  (band K-skip), out as hi/lo pair
    const dim3 ga(CDIM / 128, TDIM / 128, BDIM);             // (8, 16, 4)
    gemm_mma<2, true><<<ga, blk, SMEM_SZ>>>(ph, pl, vth, vtl, nullptr,
                                            nullptr, yh, yl, CDIM, TDIM,
                                            sTT, sTC, sTC, 0.f);

    // out = y @ Wo.T + bo (fp32)
    gemm_mma<0, false><<<gp, blk, SMEM_SZ>>>(yh, yl, woh, wol, bo,
                                             out, nullptr, nullptr, CDIM, CDIM, 0, 0, 0, 0.f);
}

// round 6
// speedup vs baseline: 3.1731x; 1.0126x over previous
#include <cuda_runtime.h>
#include <cuda_bf16.h>
#include <cstdint>

#define BDIM 4
#define TDIM 2048
#define CDIM 1024
#define WIN  16
#define NEGINF (-1e30f)

typedef __nv_bfloat16  bf16;
typedef __nv_bfloat162 bf162;

// ---------------- scratch (allocation-free rule: __device__ globals) --------
#define NTC ((size_t)BDIM * TDIM * CDIM)
#define NTT ((size_t)BDIM * TDIM * TDIM)
#define NCC ((size_t)CDIM * CDIM)
__device__ bf16  g_xh[NTC],  g_xl[NTC];
__device__ bf16  g_wqh[NCC], g_wql[NCC], g_wkh[NCC], g_wkl[NCC];
__device__ bf16  g_wvh[NCC], g_wvl[NCC], g_woh[NCC], g_wol[NCC];
__device__ bf16  g_qh[NTC],  g_ql[NTC],  g_kh[NTC],  g_kl[NTC];
__device__ float g_v[NTC];
__device__ bf16  g_vth[NTC], g_vtl[NTC];          // [b][c][t]
__device__ bf16  g_ph[NTT],  g_pl[NTT];           // unnormalized exp scores
__device__ float g_rsum[(size_t)BDIM * TDIM];     // row sums of exp
__device__ bf16  g_yh[NTC],  g_yl[NTC];

// ---------------- low-level helpers (sm_80-portable PTX only) ---------------
__device__ __forceinline__ uint32_t smem_u32(const void* p) {
    uint32_t a;
    asm("{ .reg .u64 t; cvta.to.shared.u64 t, %1; cvt.u32.u64 %0, t; }"
        : "=r"(a) : "l"(p));
    return a;
}
__device__ __forceinline__ uint32_t swz(uint32_t off) {      // SW128 swizzle
    return off ^ ((off >> 3) & 0x70);
}
__device__ __forceinline__ void cp16(uint32_t dst, const void* src) {
    asm volatile("cp.async.cg.shared.global [%0], [%1], 16;"
                 :: "r"(dst), "l"(src));
}
__device__ __forceinline__ void cp_commit() {
    asm volatile("cp.async.commit_group;" ::: "memory");
}
__device__ __forceinline__ void cp_wait2() {
    asm volatile("cp.async.wait_group 2;" ::: "memory");
}
__device__ __forceinline__ void ldsm4(uint32_t (&r)[4], uint32_t addr) {
    asm volatile("ldmatrix.sync.aligned.m8n8.x4.shared.b16 {%0,%1,%2,%3}, [%4];"
                 : "=r"(r[0]), "=r"(r[1]), "=r"(r[2]), "=r"(r[3]) : "r"(addr));
}
__device__ __forceinline__ void mma16816(float (&c)[4], const uint32_t (&a)[4],
                                         const uint32_t (&b)[2]) {
    asm volatile(
        "mma.sync.aligned.m16n8k16.row.col.f32.bf16.bf16.f32 "
        "{%0,%1,%2,%3}, {%4,%5,%6,%7}, {%8,%9}, {%0,%1,%2,%3};"
        : "+f"(c[0]), "+f"(c[1]), "+f"(c[2]), "+f"(c[3])
        : "r"(a[0]), "r"(a[1]), "r"(a[2]), "r"(a[3]), "r"(b[0]), "r"(b[1]));
}
__device__ __forceinline__ void split1(float v, bf16& h, bf16& l) {
    h = __float2bfloat16_rn(v);
    l = __float2bfloat16_rn(v - __bfloat162float(h));
}
__device__ __forceinline__ void split_store2(bf16* H, bf16* L, size_t idx,
                                             float v0, float v1) {
    bf16 h0, l0, h1, l1;
    split1(v0, h0, l0);
    split1(v1, h1, l1);
    *reinterpret_cast<bf162*>(&H[idx]) = bf162(h0, h1);
    *reinterpret_cast<bf162*>(&L[idx]) = bf162(l0, l1);
}

// ---------------------------------------------------------------------------
// Pipelined mma.sync GEMM (NT): C[m,n] = sum_k A[m,k]*B[n,k]
// A,B given as bf16 hi/lo pairs, K-major.  fp32 accuracy: AhBh+AhBl+AlBh.
// CTA 128x128, BK=64, 8 warps (4x2), warp tile 32x64, 3-stage cp.async.
// EPI 0: fp32 out + bias.
// EPI 1: scores: p=exp(scale*s) (masked->0), write hi/lo pair + row-sum atomics;
//        fully-masked tiles exit without writing (never read downstream).
// EPI 2: bf16 hi/lo pair out (+bias if non-null).
// EPI 3: AV: y = acc / rowsum[row], write hi/lo pair.
// AVSKIP: start K at m0-64 (P is exactly 0 below the band).
// ---------------------------------------------------------------------------
#define STAGE_BYTES 65536          // 4 tiles x (128 rows x 128B)
#define NSTAGE      3
#define SMEM_SZ     (NSTAGE * STAGE_BYTES)

template <int EPI, bool AVSKIP>
__global__ void __launch_bounds__(256)
gemm_mma(const bf16* __restrict__ Ah, const bf16* __restrict__ Al,
         const bf16* __restrict__ Bh, const bf16* __restrict__ Bl,
         const float* __restrict__ bias, float* __restrict__ rowsum,
         float* __restrict__ Cf, bf16* __restrict__ Ch, bf16* __restrict__ Cl,
         int N_, int K_, size_t sA, size_t sB, size_t sC, float scale)
{
    extern __shared__ __align__(1024) char smem[];
    const int bz = blockIdx.z;
    Ah += (size_t)bz * sA;  Al += (size_t)bz * sA;
    Bh += (size_t)bz * sB;  Bl += (size_t)bz * sB;
    const size_t cOff = (size_t)bz * sC;

    const int m0 = blockIdx.y * 128;
    const int n0 = blockIdx.x * 128;
    const int tid = threadIdx.x;

    if (EPI == 1) {        // fully-masked score tile: nothing to do
        if (n0 + 127 < m0 - WIN) return;
    }

    int kstart = 0;
    if (AVSKIP) kstart = (m0 >= 64) ? m0 - 64 : 0;

    const uint32_t sbase = smem_u32(smem);

    auto load_stage = [&](int stg, int k0) {
        const uint32_t sb = sbase + stg * STAGE_BYTES;
        #pragma unroll
        for (int i = 0; i < 4; i++) {
            const int id = tid + i * 256;            // 1024 16B-chunks per tile
            const int row = id >> 3, kc = id & 7;
            const uint32_t d = swz((uint32_t)(row * 128 + kc * 16));
            const size_t ga = (size_t)(m0 + row) * K_ + k0 + kc * 8;
            const size_t gb = (size_t)(n0 + row) * K_ + k0 + kc * 8;
            cp16(sb +         d, Ah + ga);
            cp16(sb + 16384 + d, Al + ga);
            cp16(sb + 32768 + d, Bh + gb);
            cp16(sb + 49152 + d, Bl + gb);
        }
    };

    const int wid = tid >> 5, lane = tid & 31;
    const int warpM = wid & 3, warpN = wid >> 2;

    float acc[2][8][4];
    #pragma unroll
    for (int i = 0; i < 2; i++)
        #pragma unroll
        for (int j = 0; j < 8; j++)
            #pragma unroll
            for (int t = 0; t < 4; t++) acc[i][j][t] = 0.0f;

    // ldmatrix per-lane base byte offsets inside a tile
    const uint32_t aoff = (uint32_t)((warpM * 32 + (lane & 15)) * 128 + (lane >> 4) * 16);
    const int bgrp = lane >> 3, bl8 = lane & 7;
    const uint32_t boff = (uint32_t)((warpN * 64 + (bgrp >> 1) * 8 + bl8) * 128 + (bgrp & 1) * 16);

    // prologue: prefetch 2 stages
    load_stage(0, kstart);
    cp_commit();
    if (kstart + 64 < K_) load_stage(1, kstart + 64);
    cp_commit();

    int stg = 0;
    for (int k0 = kstart; k0 < K_; k0 += 64) {
        const int kpre = k0 + 128;
        if (kpre < K_) {
            int sload = stg + 2;
            if (sload >= NSTAGE) sload -= NSTAGE;
            load_stage(sload, kpre);
        }
        cp_commit();
        cp_wait2();                    // stage stg complete
        __syncthreads();

        const uint32_t tb  = sbase + stg * STAGE_BYTES;
        const uint32_t tAh = tb, tAl = tb + 16384, tBh = tb + 32768, tBl = tb + 49152;

        #pragma unroll
        for (int kk = 0; kk < 4; kk++) {              // 4 k-steps of 16
            const uint32_t ka = kk * 32;              // 16 bf16 = 32 bytes
            uint32_t ah[2][4], al[2][4];
            #pragma unroll
            for (int mi = 0; mi < 2; mi++) {
                const uint32_t off = aoff + mi * 2048 + ka;
                ldsm4(ah[mi], tAh + swz(off));
                ldsm4(al[mi], tAl + swz(off));
            }
            #pragma unroll
            for (int h = 0; h < 2; h++) {             // two n-halves of 32
                uint32_t bh_[4][2], bl_[4][2];
                #pragma unroll
                for (int p = 0; p < 2; p++) {         // each ldsm4 covers 2 n-tiles
                    const uint32_t off = boff + (uint32_t)((h * 32 + p * 16) * 128) + ka;
                    uint32_t t4[4];
                    ldsm4(t4, tBh + swz(off));
                    bh_[p * 2][0] = t4[0]; bh_[p * 2][1] = t4[1];
                    bh_[p * 2 + 1][0] = t4[2]; bh_[p * 2 + 1][1] = t4[3];
                    ldsm4(t4, tBl + swz(off));
                    bl_[p * 2][0] = t4[0]; bl_[p * 2][1] = t4[1];
                    bl_[p * 2 + 1][0] = t4[2]; bl_[p * 2 + 1][1] = t4[3];
                }
                #pragma unroll
                for (int mi = 0; mi < 2; mi++)
                    #pragma unroll
                    for (int ni = 0; ni < 4; ni++) {
                        mma16816(acc[mi][h * 4 + ni], ah[mi], bh_[ni]);
                        mma16816(acc[mi][h * 4 + ni], ah[mi], bl_[ni]);
                        mma16816(acc[mi][h * 4 + ni], al[mi], bh_[ni]);
                    }
            }
        }
        __syncthreads();
        if (++stg == NSTAGE) stg = 0;
    }

    // ---- epilogue ----
    const int rbase = m0 + warpM * 32 + (lane >> 2);
    const int cbase = n0 + warpN * 64 + (lane & 3) * 2;
    #pragma unroll
    for (int mi = 0; mi < 2; mi++) {
        const int ra = rbase + mi * 16, rb = ra + 8;
        float sum_a = 0.f, sum_b = 0.f;   // EPI 1 row partial sums
        float ia = 0.f, ib = 0.f;         // EPI 3 inverse row sums
        if (EPI == 3) {
            ia = 1.0f / __ldg(&rowsum[bz * TDIM + ra]);
            ib = 1.0f / __ldg(&rowsum[bz * TDIM + rb]);
        }
        #pragma unroll
        for (int ni = 0; ni < 8; ni++) {
            const int c = cbase + ni * 8;
            float v0 = acc[mi][ni][0], v1 = acc[mi][ni][1];
            float v2 = acc[mi][ni][2], v3 = acc[mi][ni][3];
            if (EPI == 0) {
                const float b0 = bias[c], b1 = bias[c + 1];
                *reinterpret_cast<float2*>(&Cf[cOff + (size_t)ra * N_ + c]) =
                    make_float2(v0 + b0, v1 + b1);
                *reinterpret_cast<float2*>(&Cf[cOff + (size_t)rb * N_ + c]) =
                    make_float2(v2 + b0, v3 + b1);
            } else if (EPI == 1) {
                const float p0 = (c     >= ra - WIN) ? __expf(v0 * scale) : 0.f;
                const float p1 = (c + 1 >= ra - WIN) ? __expf(v1 * scale) : 0.f;
                const float p2 = (c     >= rb - WIN) ? __expf(v2 * scale) : 0.f;
                const float p3 = (c + 1 >= rb - WIN) ? __expf(v3 * scale) : 0.f;
                split_store2(Ch, Cl, cOff + (size_t)ra * N_ + c, p0, p1);
                split_store2(Ch, Cl, cOff + (size_t)rb * N_ + c, p2, p3);
                sum_a += p0 + p1;
                sum_b += p2 + p3;
            } else if (EPI == 2) {
                float b0 = 0.f, b1 = 0.f;
                if (bias) { b0 = bias[c]; b1 = bias[c + 1]; }
                split_store2(Ch, Cl, cOff + (size_t)ra * N_ + c, v0 + b0, v1 + b1);
                split_store2(Ch, Cl, cOff + (size_t)rb * N_ + c, v2 + b0, v3 + b1);
            } else {  // EPI == 3
                split_store2(Ch, Cl, cOff + (size_t)ra * N_ + c, v0 * ia, v1 * ia);
                split_store2(Ch, Cl, cOff + (size_t)rb * N_ + c, v2 * ib, v3 * ib);
            }
        }
        if (EPI == 1) {
            sum_a += __shfl_xor_sync(0xffffffffu, sum_a, 1);
            sum_a += __shfl_xor_sync(0xffffffffu, sum_a, 2);
            sum_b += __shfl_xor_sync(0xffffffffu, sum_b, 1);
            sum_b += __shfl_xor_sync(0xffffffffu, sum_b, 2);
            if ((lane & 3) == 0) {
                atomicAdd(&rowsum[bz * TDIM + ra], sum_a);
                atomicAdd(&rowsum[bz * TDIM + rb], sum_b);
            }
        }
    }
}

// ---------------------------------------------------------------------------
__global__ void __launch_bounds__(256)
zero_rowsum(float* __restrict__ r)
{
    r[blockIdx.x * 256 + threadIdx.x] = 0.0f;
}

// ---------------------------------------------------------------------------
// fp32 -> bf16 hi/lo elementwise split (vectorized by 4)
// ---------------------------------------------------------------------------
__global__ void __launch_bounds__(256)
split_kernel(const float* __restrict__ X, bf16* __restrict__ H,
             bf16* __restrict__ L, int n4)
{
    const int i = blockIdx.x * 256 + threadIdx.x;
    if (i >= n4) return;
    const float4 v = reinterpret_cast<const float4*>(X)[i];
    bf16 h0, l0, h1, l1, h2, l2, h3, l3;
    split1(v.x, h0, l0); split1(v.y, h1, l1);
    split1(v.z, h2, l2); split1(v.w, h3, l3);
    reinterpret_cast<bf162*>(H)[2 * i]     = bf162(h0, h1);
    reinterpret_cast<bf162*>(H)[2 * i + 1] = bf162(h2, h3);
    reinterpret_cast<bf162*>(L)[2 * i]     = bf162(l0, l1);
    reinterpret_cast<bf162*>(L)[2 * i + 1] = bf162(l2, l3);
}

// ---------------------------------------------------------------------------
// V transpose + split: VtH/VtL[b][c][t] = split(V[b][t][c])
// ---------------------------------------------------------------------------
__global__ void __launch_bounds__(256)
transpose_split(const float* __restrict__ V, bf16* __restrict__ TH,
                bf16* __restrict__ TL)
{
    __shared__ float t[32][33];
    const int b = blockIdx.z;
    const int c0 = blockIdx.x * 32, t0 = blockIdx.y * 32;
    const float* Vb = V + (size_t)b * TDIM * CDIM;
    bf16* THb = TH + (size_t)b * TDIM * CDIM;
    bf16* TLb = TL + (size_t)b * TDIM * CDIM;
    const int tx = threadIdx.x, ty = threadIdx.y;
    #pragma unroll
    for (int i = 0; i < 32; i += 8)
        t[ty + i][tx] = Vb[(size_t)(t0 + ty + i) * CDIM + c0 + tx];
    __syncthreads();
    #pragma unroll
    for (int i = 0; i < 32; i += 8) {
        bf16 h, l;
        split1(t[tx][ty + i], h, l);
        const size_t idx = (size_t)(c0 + ty + i) * TDIM + t0 + tx;
        THb[idx] = h;
        TLb[idx] = l;
    }
}

// ---------------------------------------------------------------------------
extern "C" void kernel_launch(void* const* d_in, const int* in_sizes, int n_in,
                              void* d_out, int out_size)
{
    const float* x  = (const float*)d_in[0];
    const float* Wq = (const float*)d_in[1];
    const float* bq = (const float*)d_in[2];
    const float* Wk = (const float*)d_in[3];
    const float* bk = (const float*)d_in[4];
    const float* Wv = (const float*)d_in[5];
    const float* bv = (const float*)d_in[6];
    const float* Wo = (const float*)d_in[7];
    const float* bo = (const float*)d_in[8];
    float* out = (float*)d_out;

    bf16 *xh, *xl, *wqh, *wql, *wkh, *wkl, *wvh, *wvl, *woh, *wol;
    bf16 *qh, *ql, *kh, *kl, *vth, *vtl, *ph, *pl, *yh, *yl;
    float *v, *rs;
    cudaGetSymbolAddress((void**)&xh, g_xh);   cudaGetSymbolAddress((void**)&xl, g_xl);
    cudaGetSymbolAddress((void**)&wqh, g_wqh); cudaGetSymbolAddress((void**)&wql, g_wql);
    cudaGetSymbolAddress((void**)&wkh, g_wkh); cudaGetSymbolAddress((void**)&wkl, g_wkl);
    cudaGetSymbolAddress((void**)&wvh, g_wvh); cudaGetSymbolAddress((void**)&wvl, g_wvl);
    cudaGetSymbolAddress((void**)&woh, g_woh); cudaGetSymbolAddress((void**)&wol, g_wol);
    cudaGetSymbolAddress((void**)&qh, g_qh);   cudaGetSymbolAddress((void**)&ql, g_ql);
    cudaGetSymbolAddress((void**)&kh, g_kh);   cudaGetSymbolAddress((void**)&kl, g_kl);
    cudaGetSymbolAddress((void**)&v, g_v);
    cudaGetSymbolAddress((void**)&vth, g_vth); cudaGetSymbolAddress((void**)&vtl, g_vtl);
    cudaGetSymbolAddress((void**)&ph, g_ph);   cudaGetSymbolAddress((void**)&pl, g_pl);
    cudaGetSymbolAddress((void**)&rs, g_rsum);
    cudaGetSymbolAddress((void**)&yh, g_yh);   cudaGetSymbolAddress((void**)&yl, g_yl);

    cudaFuncSetAttribute(gemm_mma<0, false>, cudaFuncAttributeMaxDynamicSharedMemorySize, SMEM_SZ);
    cudaFuncSetAttribute(gemm_mma<1, false>, cudaFuncAttributeMaxDynamicSharedMemorySize, SMEM_SZ);
    cudaFuncSetAttribute(gemm_mma<2, false>, cudaFuncAttributeMaxDynamicSharedMemorySize, SMEM_SZ);
    cudaFuncSetAttribute(gemm_mma<3, true >, cudaFuncAttributeMaxDynamicSharedMemorySize, SMEM_SZ);

    const dim3 blk(256);
    const float scale = 0.03125f;  // 1/sqrt(1024)
    const size_t sTC = (size_t)TDIM * CDIM;
    const size_t sTT = (size_t)TDIM * TDIM;

    // Pre-split inputs and weights into bf16 hi/lo; zero row sums
    split_kernel<<<(int)(NTC / 4 / 256), blk>>>(x, xh, xl, (int)(NTC / 4));
    split_kernel<<<(int)(NCC / 4 / 256), blk>>>(Wq, wqh, wql, (int)(NCC / 4));
    split_kernel<<<(int)(NCC / 4 / 256), blk>>>(Wk, wkh, wkl, (int)(NCC / 4));
    split_kernel<<<(int)(NCC / 4 / 256), blk>>>(Wv, wvh, wvl, (int)(NCC / 4));
    split_kernel<<<(int)(NCC / 4 / 256), blk>>>(Wo, woh, wol, (int)(NCC / 4));
    zero_rowsum<<<BDIM * TDIM / 256, blk>>>(rs);

    // Projections: q,k written as hi/lo pairs; v as fp32 (for transpose)
    const dim3 gp(CDIM / 128, (BDIM * TDIM) / 128, 1);       // (8, 64)
    gemm_mma<2, false><<<gp, blk, SMEM_SZ>>>(xh, xl, wqh, wql, bq, nullptr,
                                             nullptr, qh, ql, CDIM, CDIM, 0, 0, 0, 0.f);
    gemm_mma<2, false><<<gp, blk, SMEM_SZ>>>(xh, xl, wkh, wkl, bk, nullptr,
                                             nullptr, kh, kl, CDIM, CDIM, 0, 0, 0, 0.f);
    gemm_mma<0, false><<<gp, blk, SMEM_SZ>>>(xh, xl, wvh, wvl, bv, nullptr,
                                             v, nullptr, nullptr, CDIM, CDIM, 0, 0, 0, 0.f);

    // V transpose + split -> [b][c][t] hi/lo
    transpose_split<<<dim3(CDIM / 32, TDIM / 32, BDIM), dim3(32, 8)>>>(v, vth, vtl);

    // Scores fused with exp + mask + row-sum: P = exp(scale * q@k.T), hi/lo
    const dim3 gs(TDIM / 128, TDIM / 128, BDIM);             // (16, 16, 4)
    gemm_mma<1, false><<<gs, blk, SMEM_SZ>>>(qh, ql, kh, kl, nullptr, rs,
                                             nullptr, ph, pl, TDIM, CDIM,
                                             sTC, sTC, sTT, scale);

    // y = (P @ Vt.T) / rowsum  (band K-skip), out as hi/lo pair
    const dim3 ga(CDIM / 128, TDIM / 128, BDIM);             // (8, 16, 4)
    gemm_mma<3, true><<<ga, blk, SMEM_SZ>>>(ph, pl, vth, vtl, nullptr, rs,
                                            nullptr, yh, yl, CDIM, TDIM,
                                            sTT, sTC, sTC, 0.f);

    // out = y @ Wo.T + bo (fp32)
    gemm_mma<0, false><<<gp, blk, SMEM_SZ>>>(yh, yl, woh, wol, bo, nullptr,
                                             out, nullptr, nullptr, CDIM, CDIM, 0, 0, 0, 0.f);
}

// round 7
// speedup vs baseline: 3.3286x; 1.0490x over previous
#include <cuda_runtime.h>
#include <cuda_bf16.h>
#include <cstdint>

#define BDIM 4
#define TDIM 2048
#define CDIM 1024
#define WIN  16

typedef __nv_bfloat16  bf16;
typedef __nv_bfloat162 bf162;

// ---------------- scratch (allocation-free rule: __device__ globals) --------
#define NTC ((size_t)BDIM * TDIM * CDIM)
#define NTT ((size_t)BDIM * TDIM * TDIM)
#define NCC ((size_t)CDIM * CDIM)
__device__ bf16  g_xh[NTC],  g_xl[NTC];
__device__ bf16  g_wqh[NCC], g_wql[NCC], g_wkh[NCC], g_wkl[NCC];
__device__ bf16  g_wvh[NCC], g_wvl[NCC], g_woh[NCC], g_wol[NCC];
__device__ bf16  g_qh[NTC],  g_ql[NTC],  g_kh[NTC],  g_kl[NTC];
__device__ float g_v[NTC];
__device__ bf16  g_vth[NTC], g_vtl[NTC];          // [b][c][t]
__device__ bf16  g_ph[NTT],  g_pl[NTT];           // unnormalized exp scores
__device__ float g_rsum[(size_t)BDIM * TDIM];     // row sums of exp
__device__ bf16  g_yh[NTC],  g_yl[NTC];

// ---------------- low-level helpers (sm_80-portable PTX only) ---------------
__device__ __forceinline__ uint32_t smem_u32(const void* p) {
    uint32_t a;
    asm("{ .reg .u64 t; cvta.to.shared.u64 t, %1; cvt.u32.u64 %0, t; }"
        : "=r"(a) : "l"(p));
    return a;
}
__device__ __forceinline__ uint32_t swz(uint32_t off) {      // SW128 swizzle
    return off ^ ((off >> 3) & 0x70);
}
__device__ __forceinline__ void cp16(uint32_t dst, const void* src) {
    asm volatile("cp.async.cg.shared.global [%0], [%1], 16;"
                 :: "r"(dst), "l"(src));
}
__device__ __forceinline__ void cp_commit() {
    asm volatile("cp.async.commit_group;" ::: "memory");
}
__device__ __forceinline__ void cp_wait1() {
    asm volatile("cp.async.wait_group 1;" ::: "memory");
}
__device__ __forceinline__ void cp_wait2() {
    asm volatile("cp.async.wait_group 2;" ::: "memory");
}
__device__ __forceinline__ void ldsm4(uint32_t (&r)[4], uint32_t addr) {
    asm volatile("ldmatrix.sync.aligned.m8n8.x4.shared.b16 {%0,%1,%2,%3}, [%4];"
                 : "=r"(r[0]), "=r"(r[1]), "=r"(r[2]), "=r"(r[3]) : "r"(addr));
}
__device__ __forceinline__ void mma16816(float (&c)[4], const uint32_t (&a)[4],
                                         const uint32_t (&b)[2]) {
    asm volatile(
        "mma.sync.aligned.m16n8k16.row.col.f32.bf16.bf16.f32 "
        "{%0,%1,%2,%3}, {%4,%5,%6,%7}, {%8,%9}, {%0,%1,%2,%3};"
        : "+f"(c[0]), "+f"(c[1]), "+f"(c[2]), "+f"(c[3])
        : "r"(a[0]), "r"(a[1]), "r"(a[2]), "r"(a[3]), "r"(b[0]), "r"(b[1]));
}
__device__ __forceinline__ void split1(float v, bf16& h, bf16& l) {
    h = __float2bfloat16_rn(v);
    l = __float2bfloat16_rn(v - __bfloat162float(h));
}
__device__ __forceinline__ void split_store2(bf16* H, bf16* L, size_t idx,
                                             float v0, float v1) {
    bf16 h0, l0, h1, l1;
    split1(v0, h0, l0);
    split1(v1, h1, l1);
    *reinterpret_cast<bf162*>(&H[idx]) = bf162(h0, h1);
    *reinterpret_cast<bf162*>(&L[idx]) = bf162(l0, l1);
}

// ===========================================================================
// Projection GEMM (x @ W.T + b): CTA 256x128, warp tile 64x64, BK=64, 2-stage.
// grid.z (+zoff) selects operand set: z'=0 -> Q (bf16 hi/lo out),
// z'=1 -> K (bf16 hi/lo out), z'=2 -> fp32 out (V projection / final O).
// M = BDIM*TDIM = 8192 rows, N = K = CDIM.
// ===========================================================================
#define PSTAGE 98304            // A(hi+lo) 64KB + B(hi+lo) 32KB
#define PSMEM  (2 * PSTAGE)

__global__ void __launch_bounds__(256)
proj_mma(const bf16* __restrict__ Ah, const bf16* __restrict__ Al,
         const bf16* __restrict__ BhQ, const bf16* __restrict__ BlQ,
         const float* __restrict__ bQ, bf16* __restrict__ ChQ, bf16* __restrict__ ClQ,
         const bf16* __restrict__ BhK, const bf16* __restrict__ BlK,
         const float* __restrict__ bK, bf16* __restrict__ ChK, bf16* __restrict__ ClK,
         const bf16* __restrict__ BhV, const bf16* __restrict__ BlV,
         const float* __restrict__ bV, float* __restrict__ CfV,
         int zoff)
{
    extern __shared__ __align__(1024) char smem[];
    const int z = blockIdx.z + zoff;
    const bf16 *Bh, *Bl;
    const float* bias;
    bf16 *Ch = nullptr, *Cl = nullptr;
    float* Cf = nullptr;
    if (z == 0)      { Bh = BhQ; Bl = BlQ; bias = bQ; Ch = ChQ; Cl = ClQ; }
    else if (z == 1) { Bh = BhK; Bl = BlK; bias = bK; Ch = ChK; Cl = ClK; }
    else             { Bh = BhV; Bl = BlV; bias = bV; Cf = CfV; }

    const int m0 = blockIdx.y * 256;
    const int n0 = blockIdx.x * 128;
    const int tid = threadIdx.x;
    const uint32_t sbase = smem_u32(smem);

    auto load_stage = [&](int stg, int k0) {
        const uint32_t sb = sbase + stg * PSTAGE;
        #pragma unroll
        for (int i = 0; i < 8; i++) {                 // A: 256 rows x 128B
            const int id = tid + i * 256;
            const int row = id >> 3, kc = id & 7;
            const uint32_t d = swz((uint32_t)(row * 128 + kc * 16));
            const size_t ga = (size_t)(m0 + row) * CDIM + k0 + kc * 8;
            cp16(sb +         d, Ah + ga);
            cp16(sb + 32768 + d, Al + ga);
        }
        #pragma unroll
        for (int i = 0; i < 4; i++) {                 // B: 128 rows x 128B
            const int id = tid + i * 256;
            const int row = id >> 3, kc = id & 7;
            const uint32_t d = swz((uint32_t)(row * 128 + kc * 16));
            const size_t gb = (size_t)(n0 + row) * CDIM + k0 + kc * 8;
            cp16(sb + 65536 + d, Bh + gb);
            cp16(sb + 81920 + d, Bl + gb);
        }
    };

    const int wid = tid >> 5, lane = tid & 31;
    const int warpM = wid >> 1, warpN = wid & 1;      // 4x2 warps, 64x64 tiles

    float acc[4][8][4];
    #pragma unroll
    for (int i = 0; i < 4; i++)
        #pragma unroll
        for (int j = 0; j < 8; j++)
            #pragma unroll
            for (int t = 0; t < 4; t++) acc[i][j][t] = 0.0f;

    const uint32_t aoff = (uint32_t)((warpM * 64 + (lane & 15)) * 128 + (lane >> 4) * 16);
    const int bgrp = lane >> 3, bl8 = lane & 7;
    const uint32_t boff = (uint32_t)((warpN * 64 + (bgrp >> 1) * 8 + bl8) * 128 + (bgrp & 1) * 16);

    load_stage(0, 0);
    cp_commit();

    int stg = 0;
    for (int k0 = 0; k0 < CDIM; k0 += 64) {
        const int kn = k0 + 64;
        if (kn < CDIM) load_stage(stg ^ 1, kn);
        cp_commit();
        cp_wait1();
        __syncthreads();

        const uint32_t tb  = sbase + stg * PSTAGE;
        const uint32_t tAh = tb, tAl = tb + 32768, tBh = tb + 65536, tBl = tb + 81920;

        #pragma unroll
        for (int kk = 0; kk < 4; kk++) {
            const uint32_t ka = kk * 32;
            uint32_t ah[4][4], al[4][4];
            #pragma unroll
            for (int mi = 0; mi < 4; mi++) {
                const uint32_t off = aoff + mi * 2048 + ka;
                ldsm4(ah[mi], tAh + swz(off));
                ldsm4(al[mi], tAl + swz(off));
            }
            uint32_t bh[8][2], bl[8][2];
            #pragma unroll
            for (int p = 0; p < 4; p++) {
                const uint32_t off = boff + (uint32_t)(p * 16 * 128) + ka;
                uint32_t t4[4];
                ldsm4(t4, tBh + swz(off));
                bh[p * 2][0] = t4[0]; bh[p * 2][1] = t4[1];
                bh[p * 2 + 1][0] = t4[2]; bh[p * 2 + 1][1] = t4[3];
                ldsm4(t4, tBl + swz(off));
                bl[p * 2][0] = t4[0]; bl[p * 2][1] = t4[1];
                bl[p * 2 + 1][0] = t4[2]; bl[p * 2 + 1][1] = t4[3];
            }
            // pass-major ordering: long independent chains per pass
            #pragma unroll
            for (int mi = 0; mi < 4; mi++)
                #pragma unroll
                for (int ni = 0; ni < 8; ni++)
                    mma16816(acc[mi][ni], ah[mi], bh[ni]);
            #pragma unroll
            for (int mi = 0; mi < 4; mi++)
                #pragma unroll
                for (int ni = 0; ni < 8; ni++)
                    mma16816(acc[mi][ni], ah[mi], bl[ni]);
            #pragma unroll
            for (int mi = 0; mi < 4; mi++)
                #pragma unroll
                for (int ni = 0; ni < 8; ni++)
                    mma16816(acc[mi][ni], al[mi], bh[ni]);
        }
        __syncthreads();
        stg ^= 1;
    }

    // epilogue
    const int rbase = m0 + warpM * 64 + (lane >> 2);
    const int cbase = n0 + warpN * 64 + (lane & 3) * 2;
    #pragma unroll
    for (int mi = 0; mi < 4; mi++) {
        const int ra = rbase + mi * 16, rb = ra + 8;
        #pragma unroll
        for (int ni = 0; ni < 8; ni++) {
            const int c = cbase + ni * 8;
            const float b0 = bias[c], b1 = bias[c + 1];
            const float v0 = acc[mi][ni][0] + b0, v1 = acc[mi][ni][1] + b1;
            const float v2 = acc[mi][ni][2] + b0, v3 = acc[mi][ni][3] + b1;
            if (Cf) {
                *reinterpret_cast<float2*>(&Cf[(size_t)ra * CDIM + c]) = make_float2(v0, v1);
                *reinterpret_cast<float2*>(&Cf[(size_t)rb * CDIM + c]) = make_float2(v2, v3);
            } else {
                split_store2(Ch, Cl, (size_t)ra * CDIM + c, v0, v1);
                split_store2(Ch, Cl, (size_t)rb * CDIM + c, v2, v3);
            }
        }
    }
}

// ===========================================================================
// Scores / AV GEMM (unchanged proven 128x128 kernel): NT, 3-stage, BK=64.
// EPI 1: p=exp(scale*s) (masked->0), hi/lo out + rowsum atomics; masked tiles
//        exit without writing. EPI 3: y = acc/rowsum, hi/lo out.
// AVSKIP: start K at m0-64 (P exactly 0 below the band).
// ===========================================================================
#define STAGE_BYTES 65536
#define NSTAGE      3
#define SMEM_SZ     (NSTAGE * STAGE_BYTES)

template <int EPI, bool AVSKIP>
__global__ void __launch_bounds__(256)
gemm_mma(const bf16* __restrict__ Ah, const bf16* __restrict__ Al,
         const bf16* __restrict__ Bh, const bf16* __restrict__ Bl,
         float* __restrict__ rowsum,
         bf16* __restrict__ Ch, bf16* __restrict__ Cl,
         int N_, int K_, size_t sA, size_t sB, size_t sC, float scale)
{
    extern __shared__ __align__(1024) char smem[];
    const int bz = blockIdx.z;
    Ah += (size_t)bz * sA;  Al += (size_t)bz * sA;
    Bh += (size_t)bz * sB;  Bl += (size_t)bz * sB;
    const size_t cOff = (size_t)bz * sC;

    const int m0 = blockIdx.y * 128;
    const int n0 = blockIdx.x * 128;
    const int tid = threadIdx.x;

    if (EPI == 1) {
        if (n0 + 127 < m0 - WIN) return;     // fully masked: nothing to do
    }

    int kstart = 0;
    if (AVSKIP) kstart = (m0 >= 64) ? m0 - 64 : 0;

    const uint32_t sbase = smem_u32(smem);

    auto load_stage = [&](int stg, int k0) {
        const uint32_t sb = sbase + stg * STAGE_BYTES;
        #pragma unroll
        for (int i = 0; i < 4; i++) {
            const int id = tid + i * 256;
            const int row = id >> 3, kc = id & 7;
            const uint32_t d = swz((uint32_t)(row * 128 + kc * 16));
            const size_t ga = (size_t)(m0 + row) * K_ + k0 + kc * 8;
            const size_t gb = (size_t)(n0 + row) * K_ + k0 + kc * 8;
            cp16(sb +         d, Ah + ga);
            cp16(sb + 16384 + d, Al + ga);
            cp16(sb + 32768 + d, Bh + gb);
            cp16(sb + 49152 + d, Bl + gb);
        }
    };

    const int wid = tid >> 5, lane = tid & 31;
    const int warpM = wid & 3, warpN = wid >> 2;

    float acc[2][8][4];
    #pragma unroll
    for (int i = 0; i < 2; i++)
        #pragma unroll
        for (int j = 0; j < 8; j++)
            #pragma unroll
            for (int t = 0; t < 4; t++) acc[i][j][t] = 0.0f;

    const uint32_t aoff = (uint32_t)((warpM * 32 + (lane & 15)) * 128 + (lane >> 4) * 16);
    const int bgrp = lane >> 3, bl8 = lane & 7;
    const uint32_t boff = (uint32_t)((warpN * 64 + (bgrp >> 1) * 8 + bl8) * 128 + (bgrp & 1) * 16);

    load_stage(0, kstart);
    cp_commit();
    if (kstart + 64 < K_) load_stage(1, kstart + 64);
    cp_commit();

    int stg = 0;
    for (int k0 = kstart; k0 < K_; k0 += 64) {
        const int kpre = k0 + 128;
        if (kpre < K_) {
            int sload = stg + 2;
            if (sload >= NSTAGE) sload -= NSTAGE;
            load_stage(sload, kpre);
        }
        cp_commit();
        cp_wait2();
        __syncthreads();

        const uint32_t tb  = sbase + stg * STAGE_BYTES;
        const uint32_t tAh = tb, tAl = tb + 16384, tBh = tb + 32768, tBl = tb + 49152;

        #pragma unroll
        for (int kk = 0; kk < 4; kk++) {
            const uint32_t ka = kk * 32;
            uint32_t ah[2][4], al[2][4];
            #pragma unroll
            for (int mi = 0; mi < 2; mi++) {
                const uint32_t off = aoff + mi * 2048 + ka;
                ldsm4(ah[mi], tAh + swz(off));
                ldsm4(al[mi], tAl + swz(off));
            }
            uint32_t bh[8][2], bl[8][2];
            #pragma unroll
            for (int p = 0; p < 4; p++) {
                const uint32_t off = boff + (uint32_t)(p * 16 * 128) + ka;
                uint32_t t4[4];
                ldsm4(t4, tBh + swz(off));
                bh[p * 2][0] = t4[0]; bh[p * 2][1] = t4[1];
                bh[p * 2 + 1][0] = t4[2]; bh[p * 2 + 1][1] = t4[3];
                ldsm4(t4, tBl + swz(off));
                bl[p * 2][0] = t4[0]; bl[p * 2][1] = t4[1];
                bl[p * 2 + 1][0] = t4[2]; bl[p * 2 + 1][1] = t4[3];
            }
            #pragma unroll
            for (int mi = 0; mi < 2; mi++)
                #pragma unroll
                for (int ni = 0; ni < 8; ni++)
                    mma16816(acc[mi][ni], ah[mi], bh[ni]);
            #pragma unroll
            for (int mi = 0; mi < 2; mi++)
                #pragma unroll
                for (int ni = 0; ni < 8; ni++)
                    mma16816(acc[mi][ni], ah[mi], bl[ni]);
            #pragma unroll
            for (int mi = 0; mi < 2; mi++)
                #pragma unroll
                for (int ni = 0; ni < 8; ni++)
                    mma16816(acc[mi][ni], al[mi], bh[ni]);
        }
        __syncthreads();
        if (++stg == NSTAGE) stg = 0;
    }

    // ---- epilogue ----
    const int rbase = m0 + warpM * 32 + (lane >> 2);
    const int cbase = n0 + warpN * 64 + (lane & 3) * 2;
    #pragma unroll
    for (int mi = 0; mi < 2; mi++) {
        const int ra = rbase + mi * 16, rb = ra + 8;
        float sum_a = 0.f, sum_b = 0.f;
        float ia = 0.f, ib = 0.f;
        if (EPI == 3) {
            ia = 1.0f / __ldg(&rowsum[bz * TDIM + ra]);
            ib = 1.0f / __ldg(&rowsum[bz * TDIM + rb]);
        }
        #pragma unroll
        for (int ni = 0; ni < 8; ni++) {
            const int c = cbase + ni * 8;
            const float v0 = acc[mi][ni][0], v1 = acc[mi][ni][1];
            const float v2 = acc[mi][ni][2], v3 = acc[mi][ni][3];
            if (EPI == 1) {
                const float p0 = (c     >= ra - WIN) ? __expf(v0 * scale) : 0.f;
                const float p1 = (c + 1 >= ra - WIN) ? __expf(v1 * scale) : 0.f;
                const float p2 = (c     >= rb - WIN) ? __expf(v2 * scale) : 0.f;
                const float p3 = (c + 1 >= rb - WIN) ? __expf(v3 * scale) : 0.f;
                split_store2(Ch, Cl, cOff + (size_t)ra * N_ + c, p0, p1);
                split_store2(Ch, Cl, cOff + (size_t)rb * N_ + c, p2, p3);
                sum_a += p0 + p1;
                sum_b += p2 + p3;
            } else {  // EPI == 3
                split_store2(Ch, Cl, cOff + (size_t)ra * N_ + c, v0 * ia, v1 * ia);
                split_store2(Ch, Cl, cOff + (size_t)rb * N_ + c, v2 * ib, v3 * ib);
            }
        }
        if (EPI == 1) {
            sum_a += __shfl_xor_sync(0xffffffffu, sum_a, 1);
            sum_a += __shfl_xor_sync(0xffffffffu, sum_a, 2);
            sum_b += __shfl_xor_sync(0xffffffffu, sum_b, 1);
            sum_b += __shfl_xor_sync(0xffffffffu, sum_b, 2);
            if ((lane & 3) == 0) {
                atomicAdd(&rowsum[bz * TDIM + ra], sum_a);
                atomicAdd(&rowsum[bz * TDIM + rb], sum_b);
            }
        }
    }
}

// ---------------------------------------------------------------------------
__global__ void __launch_bounds__(256)
zero_rowsum(float* __restrict__ r)
{
    r[blockIdx.x * 256 + threadIdx.x] = 0.0f;
}

// ---------------------------------------------------------------------------
// One-shot fp32 -> bf16 hi/lo split of x + all four weights (float4 units)
// ---------------------------------------------------------------------------
__global__ void __launch_bounds__(256)
split_all(const float* __restrict__ x,  const float* __restrict__ Wq,
          const float* __restrict__ Wk, const float* __restrict__ Wv,
          const float* __restrict__ Wo,
          bf16* __restrict__ xh,  bf16* __restrict__ xl,
          bf16* __restrict__ qh,  bf16* __restrict__ ql,
          bf16* __restrict__ kh,  bf16* __restrict__ kl,
          bf16* __restrict__ vh,  bf16* __restrict__ vl,
          bf16* __restrict__ oh,  bf16* __restrict__ ol)
{
    const size_t nX = NTC / 4, nW = NCC / 4;
    size_t i = (size_t)blockIdx.x * 256 + threadIdx.x;
    const float* src;
    bf16 *H, *L;
    size_t j;
    if (i < nX)               { src = x;  H = xh; L = xl; j = i; }
    else if (i < nX + nW)     { src = Wq; H = qh; L = ql; j = i - nX; }
    else if (i < nX + 2 * nW) { src = Wk; H = kh; L = kl; j = i - nX - nW; }
    else if (i < nX + 3 * nW) { src = Wv; H = vh; L = vl; j = i - nX - 2 * nW; }
    else                      { src = Wo; H = oh; L = ol; j = i - nX - 3 * nW; }
    const float4 v = reinterpret_cast<const float4*>(src)[j];
    bf16 h0, l0, h1, l1, h2, l2, h3, l3;
    split1(v.x, h0, l0); split1(v.y, h1, l1);
    split1(v.z, h2, l2); split1(v.w, h3, l3);
    reinterpret_cast<bf162*>(H)[2 * j]     = bf162(h0, h1);
    reinterpret_cast<bf162*>(H)[2 * j + 1] = bf162(h2, h3);
    reinterpret_cast<bf162*>(L)[2 * j]     = bf162(l0, l1);
    reinterpret_cast<bf162*>(L)[2 * j + 1] = bf162(l2, l3);
}

// ---------------------------------------------------------------------------
// V transpose + split: VtH/VtL[b][c][t] = split(V[b][t][c])
// ---------------------------------------------------------------------------
__global__ void __launch_bounds__(256)
transpose_split(const float* __restrict__ V, bf16* __restrict__ TH,
                bf16* __restrict__ TL)
{
    __shared__ float t[32][33];
    const int b = blockIdx.z;
    const int c0 = blockIdx.x * 32, t0 = blockIdx.y * 32;
    const float* Vb = V + (size_t)b * TDIM * CDIM;
    bf16* THb = TH + (size_t)b * TDIM * CDIM;
    bf16* TLb = TL + (size_t)b * TDIM * CDIM;
    const int tx = threadIdx.x, ty = threadIdx.y;
    #pragma unroll
    for (int i = 0; i < 32; i += 8)
        t[ty + i][tx] = Vb[(size_t)(t0 + ty + i) * CDIM + c0 + tx];
    __syncthreads();
    #pragma unroll
    for (int i = 0; i < 32; i += 8) {
        bf16 h, l;
        split1(t[tx][ty + i], h, l);
        const size_t idx = (size_t)(c0 + ty + i) * TDIM + t0 + tx;
        THb[idx] = h;
        TLb[idx] = l;
    }
}

// ---------------------------------------------------------------------------
extern "C" void kernel_launch(void* const* d_in, const int* in_sizes, int n_in,
                              void* d_out, int out_size)
{
    const float* x  = (const float*)d_in[0];
    const float* Wq = (const float*)d_in[1];
    const float* bq = (const float*)d_in[2];
    const float* Wk = (const float*)d_in[3];
    const float* bk = (const float*)d_in[4];
    const float* Wv = (const float*)d_in[5];
    const float* bv = (const float*)d_in[6];
    const float* Wo = (const float*)d_in[7];
    const float* bo = (const float*)d_in[8];
    float* out = (float*)d_out;

    bf16 *xh, *xl, *wqh, *wql, *wkh, *wkl, *wvh, *wvl, *woh, *wol;
    bf16 *qh, *ql, *kh, *kl, *vth, *vtl, *ph, *pl, *yh, *yl;
    float *v, *rs;
    cudaGetSymbolAddress((void**)&xh, g_xh);   cudaGetSymbolAddress((void**)&xl, g_xl);
    cudaGetSymbolAddress((void**)&wqh, g_wqh); cudaGetSymbolAddress((void**)&wql, g_wql);
    cudaGetSymbolAddress((void**)&wkh, g_wkh); cudaGetSymbolAddress((void**)&wkl, g_wkl);
    cudaGetSymbolAddress((void**)&wvh, g_wvh); cudaGetSymbolAddress((void**)&wvl, g_wvl);
    cudaGetSymbolAddress((void**)&woh, g_woh); cudaGetSymbolAddress((void**)&wol, g_wol);
    cudaGetSymbolAddress((void**)&qh, g_qh);   cudaGetSymbolAddress((void**)&ql, g_ql);
    cudaGetSymbolAddress((void**)&kh, g_kh);   cudaGetSymbolAddress((void**)&kl, g_kl);
    cudaGetSymbolAddress((void**)&v, g_v);
    cudaGetSymbolAddress((void**)&vth, g_vth); cudaGetSymbolAddress((void**)&vtl, g_vtl);
    cudaGetSymbolAddress((void**)&ph, g_ph);   cudaGetSymbolAddress((void**)&pl, g_pl);
    cudaGetSymbolAddress((void**)&rs, g_rsum);
    cudaGetSymbolAddress((void**)&yh, g_yh);   cudaGetSymbolAddress((void**)&yl, g_yl);

    cudaFuncSetAttribute(proj_mma,          cudaFuncAttributeMaxDynamicSharedMemorySize, PSMEM);
    cudaFuncSetAttribute(gemm_mma<1, false>, cudaFuncAttributeMaxDynamicSharedMemorySize, SMEM_SZ);
    cudaFuncSetAttribute(gemm_mma<3, true >, cudaFuncAttributeMaxDynamicSharedMemorySize, SMEM_SZ);

    const dim3 blk(256);
    const float scale = 0.03125f;  // 1/sqrt(1024)
    const size_t sTC = (size_t)TDIM * CDIM;
    const size_t sTT = (size_t)TDIM * TDIM;

    // One-shot splits + rowsum zero
    const size_t nSplit = NTC / 4 + 4 * (NCC / 4);
    split_all<<<(int)(nSplit / 256), blk>>>(x, Wq, Wk, Wv, Wo,
                                            xh, xl, wqh, wql, wkh, wkl,
                                            wvh, wvl, woh, wol);
    zero_rowsum<<<BDIM * TDIM / 256, blk>>>(rs);

    // Merged Q/K/V projections (z selects operand set)
    const dim3 gqkv(CDIM / 128, (BDIM * TDIM) / 256, 3);     // (8, 32, 3)
    proj_mma<<<gqkv, blk, PSMEM>>>(xh, xl,
                                   wqh, wql, bq, qh, ql,
                                   wkh, wkl, bk, kh, kl,
                                   wvh, wvl, bv, v, 0);

    // V transpose + split -> [b][c][t] hi/lo
    transpose_split<<<dim3(CDIM / 32, TDIM / 32, BDIM), dim3(32, 8)>>>(v, vth, vtl);

    // Scores fused with exp + mask + row-sum: P = exp(scale * q@k.T), hi/lo
    const dim3 gs(TDIM / 128, TDIM / 128, BDIM);             // (16, 16, 4)
    gemm_mma<1, false><<<gs, blk, SMEM_SZ>>>(qh, ql, kh, kl, rs, ph, pl,
                                             TDIM, CDIM, sTC, sTC, sTT, scale);

    // y = (P @ Vt.T) / rowsum  (band K-skip), out as hi/lo pair
    const dim3 ga(CDIM / 128, TDIM / 128, BDIM);             // (8, 16, 4)
    gemm_mma<3, true><<<ga, blk, SMEM_SZ>>>(ph, pl, vth, vtl, rs, yh, yl,
                                            CDIM, TDIM, sTT, sTC, sTC, 0.f);

    // out = y @ Wo.T + bo (fp32), via the z=2 slot of proj_mma
    const dim3 go(CDIM / 128, (BDIM * TDIM) / 256, 1);       // (8, 32, 1)
    proj_mma<<<go, blk, PSMEM>>>(yh, yl,
                                 nullptr, nullptr, bo, nullptr, nullptr,
                                 nullptr, nullptr, bo, nullptr, nullptr,
                                 woh, wol, bo, out, 2);
}